// round 16
// baseline (speedup 1.0000x reference)
#include <cuda_runtime.h>

// BatchBlur: per-sample 15x15 depthwise blur with reflect pad.
// x: (32,3,512,512) f32, kernel: (32,15,15) f32, out: (32,3,512,512) f32.
// R9: R8 compute structure (8px x 4 rows/thread, quad-packed taps) plus
//  - double-buffered window with next-row LDS prefetch (hide LDS latency)
//  - MLP-4 batched prologue LDG (hide DRAM latency)
//  - launch_bounds(128,4) for the ~110-reg live set.

#define BB 32
#define CC 3
#define HH 512
#define WW 512
#define LL 15
#define PP 7

#define TW 128                  // 16 threads x, 8 px each
#define TH 32                   // 8 threads y, 4 rows each
#define IN_ROWS (TH + LL - 1)   // 46
#define CH_ROW 41               // 16B chunks per smem row (odd -> row shift)
#define ROW_F (CH_ROW * 4)      // 164 floats per smem row
#define NCH 36                  // loaded chunks per row (f = 0..143)
#define NSTEP 18                // input rows per thread

__device__ __forceinline__ int reflect_idx(int i, int n) {
    i = i < 0 ? -i : i;
    return i >= n ? 2 * n - 2 - i : i;
}

__global__ __launch_bounds__(128, 4) void batchblur_kernel(
    const float* __restrict__ x, const float* __restrict__ ker,
    float* __restrict__ out) {
    __shared__ __align__(16) float s_in[IN_ROWS * ROW_F];
    // s_kq[s][dx] = (k[s], k[s-1], k[s-2], k[s-3]) (zero when out of range)
    __shared__ __align__(16) float4 s_kq[NSTEP * 16];

    const int tid = threadIdx.x;
    const int tx = tid & 15;     // 16 threads across x, 8 px each
    const int tyi = tid >> 4;    // 8 threads across y, 4 rows each

    const int x0 = blockIdx.x * TW;
    const int y0 = blockIdx.y * TH;
    const int img = blockIdx.z;  // b*3 + c
    const int b = img / CC;

    const float* xin = x + (size_t)img * (HH * WW);
    const float* kb = ker + b * (LL * LL);

    // quad-packed taps
    for (int i = tid; i < NSTEP * 16; i += 128) {
        int s = i >> 4, dx = i & 15;
        float4 t = make_float4(0.f, 0.f, 0.f, 0.f);
        if (dx < 15) {
            if (s <= 14) t.x = kb[s * LL + dx];
            if (s >= 1 && s <= 15) t.y = kb[(s - 1) * LL + dx];
            if (s >= 2 && s <= 16) t.z = kb[(s - 2) * LL + dx];
            if (s >= 3) t.w = kb[(s - 3) * LL + dx];
        }
        s_kq[i] = t;
    }

    // ---- tile load: vector path, MLP-4 batched (tile f covers gx=x0-8+f) ----
    {
        const int cLo = (blockIdx.x == 0) ? 2 : 0;
        const int cHi = (blockIdx.x == (int)gridDim.x - 1) ? 33 : 35;
        const int total = IN_ROWS * NCH;   // 1656
        int idx = tid;
#pragma unroll 1
        for (; idx + 3 * 128 < total; idx += 4 * 128) {
            float4 v[4];
            int sq[4];
            bool ok[4];
#pragma unroll
            for (int u = 0; u < 4; u++) {
                int id = idx + u * 128;
                int r = id / NCH;
                int c = id - r * NCH;
                ok[u] = (c >= cLo) && (c <= cHi);
                int cc = ok[u] ? c : cLo;   // safe in-bounds chunk
                int gy = reflect_idx(y0 + r - PP, HH);
                v[u] = *reinterpret_cast<const float4*>(
                    xin + (size_t)gy * WW + (x0 - 8 + 4 * cc));
                int q = c ^ ((c >> 3) & 7);
                sq[u] = r * ROW_F + (q << 2);
            }
#pragma unroll
            for (int u = 0; u < 4; u++)
                if (ok[u]) *reinterpret_cast<float4*>(s_in + sq[u]) = v[u];
        }
#pragma unroll 1
        for (; idx < total; idx += 128) {
            int r = idx / NCH;
            int c = idx - r * NCH;
            if (c >= cLo && c <= cHi) {
                int gy = reflect_idx(y0 + r - PP, HH);
                float4 v = *reinterpret_cast<const float4*>(
                    xin + (size_t)gy * WW + (x0 - 8 + 4 * c));
                int q = c ^ ((c >> 3) & 7);
                *reinterpret_cast<float4*>(s_in + r * ROW_F + (q << 2)) = v;
            }
        }
        // scalar edges (reflect in x)
        if (blockIdx.x == 0) {
            for (int idx2 = tid; idx2 < IN_ROWS * 8; idx2 += 128) {
                int r = idx2 >> 3, f = idx2 & 7;      // f=0..7, c=0..1, q=c
                int gy = reflect_idx(y0 + r - PP, HH);
                s_in[r * ROW_F + f] = xin[(size_t)gy * WW + (8 - f)];
            }
        } else if (blockIdx.x == (int)gridDim.x - 1) {
            for (int idx2 = tid; idx2 < IN_ROWS * 8; idx2 += 128) {
                int r = idx2 >> 3, f = 136 + (idx2 & 7);  // c = 34..35
                int gy = reflect_idx(y0 + r - PP, HH);
                int c = f >> 2;
                int q = c ^ 4;                            // 34->38, 35->39
                int gx = 2 * WW - 2 - (x0 - 8 + f);       // reflect
                s_in[r * ROW_F + (q << 2) + (f & 3)] = xin[(size_t)gy * WW + gx];
            }
        }
    }
    __syncthreads();

    // swizzled float offsets of this thread's 6 window chunks
    int woff[6];
#pragma unroll
    for (int j = 0; j < 6; j++) {
        int c = 2 * tx + j;
        woff[j] = (c ^ ((c >> 3) & 7)) << 2;
    }

    float wA[24], wB[24];
    float aA[8], aB[8], aC[8], aD[8];
#pragma unroll
    for (int i = 0; i < 8; i++) { aA[i] = 0.f; aB[i] = 0.f; aC[i] = 0.f; aD[i] = 0.f; }

    const float* rowbase = s_in + (size_t)(4 * tyi) * ROW_F;

#define LOADW(wdst, s)                                                    \
    {                                                                     \
        const float* rp_ = rowbase + (s) * ROW_F;                         \
        _Pragma("unroll") for (int j = 0; j < 6; j++) {                   \
            float4 v_ = *reinterpret_cast<const float4*>(rp_ + woff[j]);  \
            (wdst)[4 * j + 0] = v_.x; (wdst)[4 * j + 1] = v_.y;           \
            (wdst)[4 * j + 2] = v_.z; (wdst)[4 * j + 3] = v_.w;           \
        }                                                                 \
    }

    // FMAs for step s using window wc; prefetch row s+1 into wn first.
#define STEPP(s, wc, wn, DA, DB, DC, DD, PF)                              \
    {                                                                     \
        if (PF) LOADW(wn, (s) + 1);                                       \
        const float4* kq_ = s_kq + ((s) << 4);                            \
        _Pragma("unroll") for (int dx = 0; dx < 15; dx++) {               \
            float4 t_ = kq_[dx];                                          \
            _Pragma("unroll") for (int p = 0; p < 8; p++) {               \
                if (DA) aA[p] = fmaf((wc)[1 + dx + p], t_.x, aA[p]);      \
                if (DB) aB[p] = fmaf((wc)[1 + dx + p], t_.y, aB[p]);      \
                if (DC) aC[p] = fmaf((wc)[1 + dx + p], t_.z, aC[p]);      \
                if (DD) aD[p] = fmaf((wc)[1 + dx + p], t_.w, aD[p]);      \
            }                                                             \
        }                                                                 \
    }

    LOADW(wA, 0);
    STEPP(0, wA, wB, true, false, false, false, true);
    STEPP(1, wB, wA, true, true, false, false, true);
    STEPP(2, wA, wB, true, true, true, false, true);
#pragma unroll 1
    for (int s = 3; s < 15; s += 2) {
        STEPP(s, wB, wA, true, true, true, true, true);
        STEPP(s + 1, wA, wB, true, true, true, true, true);
    }
    STEPP(15, wB, wA, false, true, true, true, true);
    STEPP(16, wA, wB, false, false, true, true, true);
    STEPP(17, wB, wA, false, false, false, true, false);

    // stores: 16 lanes x 32B contiguous per row, 4 rows
    float* o = out + (size_t)img * (HH * WW) + (size_t)(y0 + 4 * tyi) * WW +
               x0 + 8 * tx;
    *reinterpret_cast<float4*>(o)          = make_float4(aA[0], aA[1], aA[2], aA[3]);
    *reinterpret_cast<float4*>(o + 4)      = make_float4(aA[4], aA[5], aA[6], aA[7]);
    *reinterpret_cast<float4*>(o + WW)     = make_float4(aB[0], aB[1], aB[2], aB[3]);
    *reinterpret_cast<float4*>(o + WW + 4) = make_float4(aB[4], aB[5], aB[6], aB[7]);
    *reinterpret_cast<float4*>(o + 2 * WW)     = make_float4(aC[0], aC[1], aC[2], aC[3]);
    *reinterpret_cast<float4*>(o + 2 * WW + 4) = make_float4(aC[4], aC[5], aC[6], aC[7]);
    *reinterpret_cast<float4*>(o + 3 * WW)     = make_float4(aD[0], aD[1], aD[2], aD[3]);
    *reinterpret_cast<float4*>(o + 3 * WW + 4) = make_float4(aD[4], aD[5], aD[6], aD[7]);
}

extern "C" void kernel_launch(void* const* d_in, const int* in_sizes, int n_in,
                              void* d_out, int out_size) {
    const float* x = (const float*)d_in[0];
    const float* k = (const float*)d_in[1];
    float* out = (float*)d_out;
    dim3 grid(WW / TW, HH / TH, BB * CC);
    batchblur_kernel<<<grid, 128>>>(x, k, out);
}

// round 17
// speedup vs baseline: 1.0019x; 1.0019x over previous
#include <cuda_runtime.h>

// BatchBlur: per-sample 15x15 depthwise blur with reflect pad.
// x: (32,3,512,512) f32, kernel: (32,15,15) f32, out: (32,3,512,512) f32.
// R9: R8 compute structure (8px x 4 rows/thread, quad-packed taps) plus
//  - double-buffered window with next-row LDS prefetch (hide LDS latency)
//  - MLP-4 batched prologue LDG (hide DRAM latency)
//  - launch_bounds(128,4) for the ~110-reg live set.

#define BB 32
#define CC 3
#define HH 512
#define WW 512
#define LL 15
#define PP 7

#define TW 128                  // 16 threads x, 8 px each
#define TH 32                   // 8 threads y, 4 rows each
#define IN_ROWS (TH + LL - 1)   // 46
#define CH_ROW 41               // 16B chunks per smem row (odd -> row shift)
#define ROW_F (CH_ROW * 4)      // 164 floats per smem row
#define NCH 36                  // loaded chunks per row (f = 0..143)
#define NSTEP 18                // input rows per thread

__device__ __forceinline__ int reflect_idx(int i, int n) {
    i = i < 0 ? -i : i;
    return i >= n ? 2 * n - 2 - i : i;
}

__global__ __launch_bounds__(128, 4) void batchblur_kernel(
    const float* __restrict__ x, const float* __restrict__ ker,
    float* __restrict__ out) {
    __shared__ __align__(16) float s_in[IN_ROWS * ROW_F];
    // s_kq[s][dx] = (k[s], k[s-1], k[s-2], k[s-3]) (zero when out of range)
    __shared__ __align__(16) float4 s_kq[NSTEP * 16];

    const int tid = threadIdx.x;
    const int tx = tid & 15;     // 16 threads across x, 8 px each
    const int tyi = tid >> 4;    // 8 threads across y, 4 rows each

    const int x0 = blockIdx.x * TW;
    const int y0 = blockIdx.y * TH;
    const int img = blockIdx.z;  // b*3 + c
    const int b = img / CC;

    const float* xin = x + (size_t)img * (HH * WW);
    const float* kb = ker + b * (LL * LL);

    // quad-packed taps
    for (int i = tid; i < NSTEP * 16; i += 128) {
        int s = i >> 4, dx = i & 15;
        float4 t = make_float4(0.f, 0.f, 0.f, 0.f);
        if (dx < 15) {
            if (s <= 14) t.x = kb[s * LL + dx];
            if (s >= 1 && s <= 15) t.y = kb[(s - 1) * LL + dx];
            if (s >= 2 && s <= 16) t.z = kb[(s - 2) * LL + dx];
            if (s >= 3) t.w = kb[(s - 3) * LL + dx];
        }
        s_kq[i] = t;
    }

    // ---- tile load: vector path, MLP-4 batched (tile f covers gx=x0-8+f) ----
    {
        const int cLo = (blockIdx.x == 0) ? 2 : 0;
        const int cHi = (blockIdx.x == (int)gridDim.x - 1) ? 33 : 35;
        const int total = IN_ROWS * NCH;   // 1656
        int idx = tid;
#pragma unroll 1
        for (; idx + 3 * 128 < total; idx += 4 * 128) {
            float4 v[4];
            int sq[4];
            bool ok[4];
#pragma unroll
            for (int u = 0; u < 4; u++) {
                int id = idx + u * 128;
                int r = id / NCH;
                int c = id - r * NCH;
                ok[u] = (c >= cLo) && (c <= cHi);
                int cc = ok[u] ? c : cLo;   // safe in-bounds chunk
                int gy = reflect_idx(y0 + r - PP, HH);
                v[u] = *reinterpret_cast<const float4*>(
                    xin + (size_t)gy * WW + (x0 - 8 + 4 * cc));
                int q = c ^ ((c >> 3) & 7);
                sq[u] = r * ROW_F + (q << 2);
            }
#pragma unroll
            for (int u = 0; u < 4; u++)
                if (ok[u]) *reinterpret_cast<float4*>(s_in + sq[u]) = v[u];
        }
#pragma unroll 1
        for (; idx < total; idx += 128) {
            int r = idx / NCH;
            int c = idx - r * NCH;
            if (c >= cLo && c <= cHi) {
                int gy = reflect_idx(y0 + r - PP, HH);
                float4 v = *reinterpret_cast<const float4*>(
                    xin + (size_t)gy * WW + (x0 - 8 + 4 * c));
                int q = c ^ ((c >> 3) & 7);
                *reinterpret_cast<float4*>(s_in + r * ROW_F + (q << 2)) = v;
            }
        }
        // scalar edges (reflect in x)
        if (blockIdx.x == 0) {
            for (int idx2 = tid; idx2 < IN_ROWS * 8; idx2 += 128) {
                int r = idx2 >> 3, f = idx2 & 7;      // f=0..7, c=0..1, q=c
                int gy = reflect_idx(y0 + r - PP, HH);
                s_in[r * ROW_F + f] = xin[(size_t)gy * WW + (8 - f)];
            }
        } else if (blockIdx.x == (int)gridDim.x - 1) {
            for (int idx2 = tid; idx2 < IN_ROWS * 8; idx2 += 128) {
                int r = idx2 >> 3, f = 136 + (idx2 & 7);  // c = 34..35
                int gy = reflect_idx(y0 + r - PP, HH);
                int c = f >> 2;
                int q = c ^ 4;                            // 34->38, 35->39
                int gx = 2 * WW - 2 - (x0 - 8 + f);       // reflect
                s_in[r * ROW_F + (q << 2) + (f & 3)] = xin[(size_t)gy * WW + gx];
            }
        }
    }
    __syncthreads();

    // swizzled float offsets of this thread's 6 window chunks
    int woff[6];
#pragma unroll
    for (int j = 0; j < 6; j++) {
        int c = 2 * tx + j;
        woff[j] = (c ^ ((c >> 3) & 7)) << 2;
    }

    float wA[24], wB[24];
    float aA[8], aB[8], aC[8], aD[8];
#pragma unroll
    for (int i = 0; i < 8; i++) { aA[i] = 0.f; aB[i] = 0.f; aC[i] = 0.f; aD[i] = 0.f; }

    const float* rowbase = s_in + (size_t)(4 * tyi) * ROW_F;

#define LOADW(wdst, s)                                                    \
    {                                                                     \
        const float* rp_ = rowbase + (s) * ROW_F;                         \
        _Pragma("unroll") for (int j = 0; j < 6; j++) {                   \
            float4 v_ = *reinterpret_cast<const float4*>(rp_ + woff[j]);  \
            (wdst)[4 * j + 0] = v_.x; (wdst)[4 * j + 1] = v_.y;           \
            (wdst)[4 * j + 2] = v_.z; (wdst)[4 * j + 3] = v_.w;           \
        }                                                                 \
    }

    // FMAs for step s using window wc; prefetch row s+1 into wn first.
#define STEPP(s, wc, wn, DA, DB, DC, DD, PF)                              \
    {                                                                     \
        if (PF) LOADW(wn, (s) + 1);                                       \
        const float4* kq_ = s_kq + ((s) << 4);                            \
        _Pragma("unroll") for (int dx = 0; dx < 15; dx++) {               \
            float4 t_ = kq_[dx];                                          \
            _Pragma("unroll") for (int p = 0; p < 8; p++) {               \
                if (DA) aA[p] = fmaf((wc)[1 + dx + p], t_.x, aA[p]);      \
                if (DB) aB[p] = fmaf((wc)[1 + dx + p], t_.y, aB[p]);      \
                if (DC) aC[p] = fmaf((wc)[1 + dx + p], t_.z, aC[p]);      \
                if (DD) aD[p] = fmaf((wc)[1 + dx + p], t_.w, aD[p]);      \
            }                                                             \
        }                                                                 \
    }

    LOADW(wA, 0);
    STEPP(0, wA, wB, true, false, false, false, true);
    STEPP(1, wB, wA, true, true, false, false, true);
    STEPP(2, wA, wB, true, true, true, false, true);
#pragma unroll 1
    for (int s = 3; s < 15; s += 2) {
        STEPP(s, wB, wA, true, true, true, true, true);
        STEPP(s + 1, wA, wB, true, true, true, true, true);
    }
    STEPP(15, wB, wA, false, true, true, true, true);
    STEPP(16, wA, wB, false, false, true, true, true);
    STEPP(17, wB, wA, false, false, false, true, false);

    // stores: 16 lanes x 32B contiguous per row, 4 rows
    float* o = out + (size_t)img * (HH * WW) + (size_t)(y0 + 4 * tyi) * WW +
               x0 + 8 * tx;
    *reinterpret_cast<float4*>(o)          = make_float4(aA[0], aA[1], aA[2], aA[3]);
    *reinterpret_cast<float4*>(o + 4)      = make_float4(aA[4], aA[5], aA[6], aA[7]);
    *reinterpret_cast<float4*>(o + WW)     = make_float4(aB[0], aB[1], aB[2], aB[3]);
    *reinterpret_cast<float4*>(o + WW + 4) = make_float4(aB[4], aB[5], aB[6], aB[7]);
    *reinterpret_cast<float4*>(o + 2 * WW)     = make_float4(aC[0], aC[1], aC[2], aC[3]);
    *reinterpret_cast<float4*>(o + 2 * WW + 4) = make_float4(aC[4], aC[5], aC[6], aC[7]);
    *reinterpret_cast<float4*>(o + 3 * WW)     = make_float4(aD[0], aD[1], aD[2], aD[3]);
    *reinterpret_cast<float4*>(o + 3 * WW + 4) = make_float4(aD[4], aD[5], aD[6], aD[7]);
}

extern "C" void kernel_launch(void* const* d_in, const int* in_sizes, int n_in,
                              void* d_out, int out_size) {
    const float* x = (const float*)d_in[0];
    const float* k = (const float*)d_in[1];
    float* out = (float*)d_out;
    dim3 grid(WW / TW, HH / TH, BB * CC);
    batchblur_kernel<<<grid, 128>>>(x, k, out);
}